// round 13
// baseline (speedup 1.0000x reference)
#include <cuda_runtime.h>

#define THREADS 256
#define L 2500
#define HALF 1251          // bins 0..1250
#define PATCHES 50
#define TWN 500            // master twiddle table: W_2500^j, j=0..499
#define GROUP 128          // threads per batch in the search phase

__device__ __forceinline__ float2 cmul(float2 a, float2 b) {
    return make_float2(a.x * b.x - a.y * b.y, a.x * b.y + a.y * b.x);
}

// radix-5 constants (w = e^{-2pi i/5})
#define CR1 ( 0.30901699437494742f)
#define CR2 (-0.80901699437494742f)
#define SI1 ( 0.95105651629515357f)
#define SI2 ( 0.58778525229247314f)

// Core radix-5 DFT + twiddle + store, shared by all stages.
__device__ __forceinline__ void bf5_store(float2 a0, float2 a1, float2 a2, float2 a3, float2 a4,
                                          float2 w1, float2* __restrict__ Y, int ob, int SS) {
    float2 t1 = make_float2(a1.x + a4.x, a1.y + a4.y);
    float2 t2 = make_float2(a2.x + a3.x, a2.y + a3.y);
    float2 t3 = make_float2(a1.x - a4.x, a1.y - a4.y);
    float2 t4 = make_float2(a2.x - a3.x, a2.y - a3.y);
    float2 c0 = make_float2(a0.x + t1.x + t2.x, a0.y + t1.y + t2.y);
    float2 m1 = make_float2(a0.x + CR1 * t1.x + CR2 * t2.x, a0.y + CR1 * t1.y + CR2 * t2.y);
    float2 m2 = make_float2(a0.x + CR2 * t1.x + CR1 * t2.x, a0.y + CR2 * t1.y + CR1 * t2.y);
    float2 s1 = make_float2(SI1 * t3.x + SI2 * t4.x, SI1 * t3.y + SI2 * t4.y);
    float2 s2 = make_float2(SI2 * t3.x - SI1 * t4.x, SI2 * t3.y - SI1 * t4.y);
    float2 c1 = make_float2(m1.x + s1.y, m1.y - s1.x);
    float2 c4 = make_float2(m1.x - s1.y, m1.y + s1.x);
    float2 c2 = make_float2(m2.x + s2.y, m2.y - s2.x);
    float2 c3 = make_float2(m2.x - s2.y, m2.y + s2.x);
    float2 w2 = cmul(w1, w1);
    float2 w3 = cmul(w2, w1);
    float2 w4 = cmul(w2, w2);
    Y[ob]          = c0;
    Y[ob + SS]     = cmul(c1, w1);
    Y[ob + 2 * SS] = cmul(c2, w2);
    Y[ob + 3 * SS] = cmul(c3, w3);
    Y[ob + 4 * SS] = cmul(c4, w4);
}

// Stockham DIF radix-5 stage, natural-order autosort. WORK = 500 each.
template <int NN, int SS>
__device__ __forceinline__ void stage5(const float2* __restrict__ X, float2* __restrict__ Y,
                                       const float2* __restrict__ tw, int tid) {
    constexpr int M = NN / 5;
    constexpr int STRIDE = 2500 / NN;
    for (int w = tid; w < M * SS; w += THREADS) {
        const int q = w % SS;
        const int p = w / SS;
        bf5_store(X[q + SS * p], X[q + SS * (p + M)], X[q + SS * (p + 2 * M)],
                  X[q + SS * (p + 3 * M)], X[q + SS * (p + 4 * M)],
                  tw[p * STRIDE], Y, q + SS * 5 * p, SS);
    }
}

// Final radix-4 DIF butterfly (twiddle-free), in registers.
__device__ __forceinline__ void r4(const float2* __restrict__ A, int q,
                                   float2& z0, float2& z1, float2& z2, float2& z3) {
    float2 a0 = A[q], a1 = A[q + 625], a2 = A[q + 1250], a3 = A[q + 1875];
    float2 e0 = make_float2(a0.x + a2.x, a0.y + a2.y);
    float2 e1 = make_float2(a0.x - a2.x, a0.y - a2.y);
    float2 o0 = make_float2(a1.x + a3.x, a1.y + a3.y);
    float2 o1 = make_float2(a1.x - a3.x, a1.y - a3.y);
    z0 = make_float2(e0.x + o0.x, e0.y + o0.y);   // Z[q]
    z1 = make_float2(e1.x + o1.y, e1.y - o1.x);   // Z[q+625]   (e1 - i*o1)
    z2 = make_float2(e0.x - o0.x, e0.y - o0.y);   // Z[q+1250]
    z3 = make_float2(e1.x - o1.y, e1.y + o1.x);   // Z[q+1875]  (e1 + i*o1)
}

// Tie-aware insert into a sorted triple: value desc, index asc on ties
// (= jax.lax.top_k ordering). Guard-first: the common miss costs ~2 instrs.
__device__ __forceinline__ void ins3g(float v, int k,
                                      float& v0, int& i0, float& v1, int& i1,
                                      float& v2, int& i2) {
    if (v > v2 || (v == v2 && k < i2)) {
        if (v > v1 || (v == v1 && k < i1)) {
            v2 = v1; i2 = i1;
            if (v > v0 || (v == v0 && k < i0)) { v1 = v0; i1 = i0; v0 = v; i0 = k; }
            else { v1 = v; i1 = k; }
        } else { v2 = v; i2 = k; }
    }
}

__global__ __launch_bounds__(THREADS)
void TimeSeriesWeighting_kernel(const float* __restrict__ x,
                                const float* __restrict__ wscal,
                                float* __restrict__ out) {
    __shared__ float2 bufA[L];
    __shared__ float2 bufB[L];
    __shared__ float2 tw[TWN];
    __shared__ float mv[THREADS / 32][3];
    __shared__ int   mi[THREADS / 32][3];
    __shared__ int   top_idx[2][3];

    const int tid = threadIdx.x;
    const long long b0 = 2LL * blockIdx.x;

    // Prefetch stage-1 inputs into registers BEFORE the table fill so the
    // DRAM latency overlaps the MUFU/STS table work. Two items per thread:
    // p = tid (always valid) and p1 = tid + 256 (valid if < 500).
    const float* xa = x + b0 * 30000;
    const float* xb = xa + 30000;
    const int p1 = tid + THREADS;
    float ra[10], rb[10];
    #pragma unroll
    for (int u = 0; u < 5; u++) { ra[u] = xa[tid + u * 500]; rb[u] = xb[tid + u * 500]; }
    if (p1 < 500) {
        #pragma unroll
        for (int u = 0; u < 5; u++) { ra[5 + u] = xa[p1 + u * 500]; rb[5 + u] = xb[p1 + u * 500]; }
    }

    // Master twiddle table (MUFU sincos; ranking-safe, measured rel_err 0.0)
    for (int j = tid; j < TWN; j += THREADS) {
        float sn, cs;
        __sincosf(-6.283185307179586f * (float)j * (1.0f / 2500.0f), &sn, &cs);
        tw[j] = make_float2(cs, sn);
    }
    __syncthreads();

    // Fused stage 1 (NN=2500, SS=1) from prefetched registers: z = x_a + i*x_b
    bf5_store(make_float2(ra[0], rb[0]), make_float2(ra[1], rb[1]),
              make_float2(ra[2], rb[2]), make_float2(ra[3], rb[3]),
              make_float2(ra[4], rb[4]), tw[tid], bufB, 5 * tid, 1);
    if (p1 < 500) {
        bf5_store(make_float2(ra[5], rb[5]), make_float2(ra[6], rb[6]),
                  make_float2(ra[7], rb[7]), make_float2(ra[8], rb[8]),
                  make_float2(ra[9], rb[9]), tw[p1], bufB, 5 * p1, 1);
    }
    __syncthreads();

    // Remaining Stockham stages (natural-order autosort)
    stage5<500, 5>(bufB, bufA, tw, tid);   __syncthreads();
    stage5<100, 25>(bufA, bufB, tw, tid);  __syncthreads();
    stage5<20, 125>(bufB, bufA, tw, tid);  __syncthreads();

    // Fused final radix-4 + conjugate-split + power -> pa/pb in smem.
    // Butterflies q and 625-q jointly produce the 4 conjugate pairs covering
    // half-bins {q, 625-q, 625+q, 1250-q} (verified R10-R12):
    //   pw_a[k] ∝ |Z[k]+conj(Z[2500-k])|^2 , pw_b[k] ∝ |Z[k]-conj(Z[2500-k])|^2
    float* pa = reinterpret_cast<float*>(bufB);   // 1251 floats
    float* pb = pa + 1280;                        // 1251 floats (bufB = 5000 floats)

    #define PAIRPOW(zk, zm, kk) do {                                          \
        float sx = (zk).x + (zm).x, sy = (zk).y - (zm).y;                     \
        float dx = (zk).x - (zm).x, dy = (zk).y + (zm).y;                     \
        pa[(kk)] = sx * sx + sy * sy;                                         \
        pb[(kk)] = dx * dx + dy * dy;                                         \
    } while (0)

    for (int w = tid; w < 313; w += THREADS) {
        if (w == 0) {
            // self-paired butterfly 0: bins 0, 625 (pairs with 1875), 1250
            float2 z0, z1, z2, z3;
            r4(bufA, 0, z0, z1, z2, z3);
            PAIRPOW(z0, z0, 0);
            PAIRPOW(z1, z3, 625);
            PAIRPOW(z2, z2, 1250);
        } else {
            const int q = w;              // 1..312
            float2 q0, q1, q2, q3, p0, p1v, p2, p3;
            r4(bufA, q, q0, q1, q2, q3);
            r4(bufA, 625 - q, p0, p1v, p2, p3);
            PAIRPOW(q0, p3, q);           // Z[q]      & Z[2500-q]
            PAIRPOW(p0, q3, 625 - q);     // Z[625-q]  & Z[1875+q]
            PAIRPOW(q1, p2, 625 + q);     // Z[625+q]  & Z[1875-q]
            PAIRPOW(p1v, q2, 1250 - q);   // Z[1250-q] & Z[1250+q]
        }
    }
    #undef PAIRPOW
    __syncthreads();

    // Single-pass top-3 per batch: group 0 = threads [0,128) (batch a),
    // group 1 = threads [128,256) (batch b). Register triples + shuffle merge.
    const int g = tid >> 7;
    const int lt = tid & 127;
    const float* pw = g ? pb : pa;
    float v0 = -1.0f, v1 = -1.0f, v2 = -1.0f;
    int   j0 = 0x7fffffff, j1 = 0x7fffffff, j2 = 0x7fffffff;
    for (int k = lt; k < HALF; k += GROUP)
        ins3g(pw[k], k, v0, j0, v1, j1, v2, j2);
    #pragma unroll
    for (int off = 16; off > 0; off >>= 1) {
        float t0 = __shfl_down_sync(0xffffffffu, v0, off);
        int   m0 = __shfl_down_sync(0xffffffffu, j0, off);
        float t1 = __shfl_down_sync(0xffffffffu, v1, off);
        int   m1 = __shfl_down_sync(0xffffffffu, j1, off);
        float t2 = __shfl_down_sync(0xffffffffu, v2, off);
        int   m2 = __shfl_down_sync(0xffffffffu, j2, off);
        ins3g(t0, m0, v0, j0, v1, j1, v2, j2);
        ins3g(t1, m1, v0, j0, v1, j1, v2, j2);
        ins3g(t2, m2, v0, j0, v1, j1, v2, j2);
    }
    const int wid = tid >> 5;          // warps 0-3 -> batch a, 4-7 -> batch b
    if ((tid & 31) == 0) {
        mv[wid][0] = v0; mi[wid][0] = j0;
        mv[wid][1] = v1; mi[wid][1] = j1;
        mv[wid][2] = v2; mi[wid][2] = j2;
    }
    __syncthreads();
    if (lt == 0) {                     // tid 0 -> batch a, tid 128 -> batch b
        const int base = g * 4;
        float f0 = mv[base][0], f1 = mv[base][1], f2 = mv[base][2];
        int   e0 = mi[base][0], e1 = mi[base][1], e2 = mi[base][2];
        #pragma unroll
        for (int wq = 1; wq < 4; wq++) {
            ins3g(mv[base + wq][0], mi[base + wq][0], f0, e0, f1, e1, f2, e2);
            ins3g(mv[base + wq][1], mi[base + wq][1], f0, e0, f1, e1, f2, e2);
            ins3g(mv[base + wq][2], mi[base + wq][2], f0, e0, f1, e1, f2, e2);
        }
        top_idx[g][0] = e0; top_idx[g][1] = e1; top_idx[g][2] = e2;
    }
    __syncthreads();

    // Full-spectrum ranks {0, 2} from half-spectrum top-3 with pair multiplicity:
    // DC (0) and Nyquist (1250) appear once; other bins twice (k, 2500-k).
    const int h0 = top_idx[g][0], h1 = top_idx[g][1], h2 = top_idx[g][2];
    const bool h0_pair = (h0 != 0 && h0 != 1250);
    const bool h1_pair = (h1 != 0 && h1 != 1250);
    const int ka = h0;
    const int kb = (h0_pair || h1_pair) ? h1 : h2;

    if (lt < PATCHES) {
        const float wgt = 12.0f * wscal[0];  // N * weights
        const int start = lt * 50;
        int cnt = 0;
        if (ka != 0) {
            int p = L / ka;
            int fm = ((start + p - 1) / p) * p;
            cnt += (fm < start + 50);
        }
        if (kb != 0) {
            int p = L / kb;
            int fm = ((start + p - 1) / p) * p;
            cnt += (fm < start + 50);
        }
        out[(b0 + g) * PATCHES + lt] = wgt * (float)cnt;
    }
}

extern "C" void kernel_launch(void* const* d_in, const int* in_sizes, int n_in,
                              void* d_out, int out_size) {
    const float* x = (const float*)d_in[0];
    const float* w = (const float*)d_in[1];
    int xs = in_sizes[0];
    if (n_in >= 2 && in_sizes[0] < in_sizes[1]) {  // order-robust: scalar vs big tensor
        x = (const float*)d_in[1];
        w = (const float*)d_in[0];
        xs = in_sizes[1];
    }
    const int B = xs / (12 * L);   // 1024
    TimeSeriesWeighting_kernel<<<B / 2, THREADS>>>(x, w, (float*)d_out);
}

// round 14
// speedup vs baseline: 1.1356x; 1.1356x over previous
#include <cuda_runtime.h>

#define THREADS 256
#define L 2500
#define HALF 1251          // bins 0..1250
#define PATCHES 50
#define TWN 500            // master twiddle table: W_2500^j, j=0..499
#define GROUP 128          // threads per batch in the search phase

__device__ __forceinline__ float2 cmul(float2 a, float2 b) {
    return make_float2(a.x * b.x - a.y * b.y, a.x * b.y + a.y * b.x);
}

// radix-5 constants (w = e^{-2pi i/5})
#define CR1 ( 0.30901699437494742f)
#define CR2 (-0.80901699437494742f)
#define SI1 ( 0.95105651629515357f)
#define SI2 ( 0.58778525229247314f)

// Core radix-5 DFT + twiddle + store, shared by all stages.
__device__ __forceinline__ void bf5_store(float2 a0, float2 a1, float2 a2, float2 a3, float2 a4,
                                          float2 w1, float2* __restrict__ Y, int ob, int SS) {
    float2 t1 = make_float2(a1.x + a4.x, a1.y + a4.y);
    float2 t2 = make_float2(a2.x + a3.x, a2.y + a3.y);
    float2 t3 = make_float2(a1.x - a4.x, a1.y - a4.y);
    float2 t4 = make_float2(a2.x - a3.x, a2.y - a3.y);
    float2 c0 = make_float2(a0.x + t1.x + t2.x, a0.y + t1.y + t2.y);
    float2 m1 = make_float2(a0.x + CR1 * t1.x + CR2 * t2.x, a0.y + CR1 * t1.y + CR2 * t2.y);
    float2 m2 = make_float2(a0.x + CR2 * t1.x + CR1 * t2.x, a0.y + CR2 * t1.y + CR1 * t2.y);
    float2 s1 = make_float2(SI1 * t3.x + SI2 * t4.x, SI1 * t3.y + SI2 * t4.y);
    float2 s2 = make_float2(SI2 * t3.x - SI1 * t4.x, SI2 * t3.y - SI1 * t4.y);
    float2 c1 = make_float2(m1.x + s1.y, m1.y - s1.x);
    float2 c4 = make_float2(m1.x - s1.y, m1.y + s1.x);
    float2 c2 = make_float2(m2.x + s2.y, m2.y - s2.x);
    float2 c3 = make_float2(m2.x - s2.y, m2.y + s2.x);
    float2 w2 = cmul(w1, w1);
    float2 w3 = cmul(w2, w1);
    float2 w4 = cmul(w2, w2);
    Y[ob]          = c0;
    Y[ob + SS]     = cmul(c1, w1);
    Y[ob + 2 * SS] = cmul(c2, w2);
    Y[ob + 3 * SS] = cmul(c3, w3);
    Y[ob + 4 * SS] = cmul(c4, w4);
}

// Stockham DIF radix-5 stage, natural-order autosort. WORK = 500 each.
template <int NN, int SS>
__device__ __forceinline__ void stage5(const float2* __restrict__ X, float2* __restrict__ Y,
                                       const float2* __restrict__ tw, int tid) {
    constexpr int M = NN / 5;
    constexpr int STRIDE = 2500 / NN;
    for (int w = tid; w < M * SS; w += THREADS) {
        const int q = w % SS;
        const int p = w / SS;
        bf5_store(X[q + SS * p], X[q + SS * (p + M)], X[q + SS * (p + 2 * M)],
                  X[q + SS * (p + 3 * M)], X[q + SS * (p + 4 * M)],
                  tw[p * STRIDE], Y, q + SS * 5 * p, SS);
    }
}

// Final radix-4 DIF butterfly (twiddle-free), in registers.
__device__ __forceinline__ void r4(const float2* __restrict__ A, int q,
                                   float2& z0, float2& z1, float2& z2, float2& z3) {
    float2 a0 = A[q], a1 = A[q + 625], a2 = A[q + 1250], a3 = A[q + 1875];
    float2 e0 = make_float2(a0.x + a2.x, a0.y + a2.y);
    float2 e1 = make_float2(a0.x - a2.x, a0.y - a2.y);
    float2 o0 = make_float2(a1.x + a3.x, a1.y + a3.y);
    float2 o1 = make_float2(a1.x - a3.x, a1.y - a3.y);
    z0 = make_float2(e0.x + o0.x, e0.y + o0.y);   // Z[q]
    z1 = make_float2(e1.x + o1.y, e1.y - o1.x);   // Z[q+625]   (e1 - i*o1)
    z2 = make_float2(e0.x - o0.x, e0.y - o0.y);   // Z[q+1250]
    z3 = make_float2(e1.x - o1.y, e1.y + o1.x);   // Z[q+1875]  (e1 + i*o1)
}

__global__ __launch_bounds__(THREADS)
void TimeSeriesWeighting_kernel(const float* __restrict__ x,
                                const float* __restrict__ wscal,
                                float* __restrict__ out) {
    __shared__ float2 bufA[L];
    __shared__ float2 bufB[L];
    __shared__ float2 tw[TWN];
    __shared__ float s_v[THREADS / 32];
    __shared__ int   s_i[THREADS / 32];
    __shared__ int   top_idx[2][3];

    const int tid = threadIdx.x;
    const long long b0 = 2LL * blockIdx.x;

    // Fused load + stage 1 (NN=2500, SS=1) FIRST: gmem loads issue at cycle 0.
    // Stage-1 twiddle (tw[p], its own index) computed inline via MUFU sincos
    // instead of the table, so no barrier is needed before this loop.
    const float* xa = x + b0 * 30000;
    const float* xb = xa + 30000;
    for (int p = tid; p < 500; p += THREADS) {
        float2 a0 = make_float2(xa[p],        xb[p]);
        float2 a1 = make_float2(xa[p +  500], xb[p +  500]);
        float2 a2 = make_float2(xa[p + 1000], xb[p + 1000]);
        float2 a3 = make_float2(xa[p + 1500], xb[p + 1500]);
        float2 a4 = make_float2(xa[p + 2000], xb[p + 2000]);
        float sn, cs;
        __sincosf(-6.283185307179586f * (float)p * (1.0f / 2500.0f), &sn, &cs);
        bf5_store(a0, a1, a2, a3, a4, make_float2(cs, sn), bufB, 5 * p, 1);
    }
    // Master twiddle table fill overlaps the tail of the stage-1 gmem latency.
    for (int j = tid; j < TWN; j += THREADS) {
        float sn, cs;
        __sincosf(-6.283185307179586f * (float)j * (1.0f / 2500.0f), &sn, &cs);
        tw[j] = make_float2(cs, sn);
    }
    __syncthreads();   // single barrier covers bufB stores + table

    // Remaining Stockham stages (natural-order autosort)
    stage5<500, 5>(bufB, bufA, tw, tid);   __syncthreads();
    stage5<100, 25>(bufA, bufB, tw, tid);  __syncthreads();
    stage5<20, 125>(bufB, bufA, tw, tid);  __syncthreads();

    // Fused final radix-4 + conjugate-split + power -> pa/pb in smem.
    // Butterflies q and 625-q jointly produce the 4 conjugate pairs covering
    // half-bins {q, 625-q, 625+q, 1250-q} (verified R10-R12):
    //   pw_a[k] ∝ |Z[k]+conj(Z[2500-k])|^2 , pw_b[k] ∝ |Z[k]-conj(Z[2500-k])|^2
    float* pa = reinterpret_cast<float*>(bufB);   // 1251 floats
    float* pb = pa + 1280;                        // 1251 floats (bufB = 5000 floats)

    #define PAIRPOW(zk, zm, kk) do {                                          \
        float sx = (zk).x + (zm).x, sy = (zk).y - (zm).y;                     \
        float dx = (zk).x - (zm).x, dy = (zk).y + (zm).y;                     \
        pa[(kk)] = sx * sx + sy * sy;                                         \
        pb[(kk)] = dx * dx + dy * dy;                                         \
    } while (0)

    for (int w = tid; w < 313; w += THREADS) {
        if (w == 0) {
            // self-paired butterfly 0: bins 0, 625 (pairs with 1875), 1250
            float2 z0, z1, z2, z3;
            r4(bufA, 0, z0, z1, z2, z3);
            PAIRPOW(z0, z0, 0);
            PAIRPOW(z1, z3, 625);
            PAIRPOW(z2, z2, 1250);
        } else {
            const int q = w;              // 1..312
            float2 q0, q1, q2, q3, p0, p1v, p2, p3;
            r4(bufA, q, q0, q1, q2, q3);
            r4(bufA, 625 - q, p0, p1v, p2, p3);
            PAIRPOW(q0, p3, q);           // Z[q]      & Z[2500-q]
            PAIRPOW(p0, q3, 625 - q);     // Z[625-q]  & Z[1875+q]
            PAIRPOW(q1, p2, 625 + q);     // Z[625+q]  & Z[1875-q]
            PAIRPOW(p1v, q2, 1250 - q);   // Z[1250-q] & Z[1250+q]
        }
    }
    #undef PAIRPOW
    __syncthreads();

    // Top-3 half-spectrum bins per batch; group 0 = threads 0..127 (batch a),
    // group 1 = threads 128..255 (batch b). 3 exclusion passes (proven fastest).
    const int g = tid >> 7;
    const int lt = tid & 127;
    const float* pw = g ? pb : pa;
    for (int r = 0; r < 3; r++) {
        const int e0 = (r > 0) ? top_idx[g][0] : -1;
        const int e1 = (r > 1) ? top_idx[g][1] : -1;
        float bv = -1.0f;
        int bi = 0x7fffffff;
        for (int k = lt; k < HALF; k += GROUP) {
            if (k == e0 || k == e1) continue;
            float v = pw[k];
            if (v > bv || (v == bv && k < bi)) { bv = v; bi = k; }
        }
        #pragma unroll
        for (int off = 16; off > 0; off >>= 1) {
            float ov = __shfl_down_sync(0xffffffffu, bv, off);
            int   oi = __shfl_down_sync(0xffffffffu, bi, off);
            if (ov > bv || (ov == bv && oi < bi)) { bv = ov; bi = oi; }
        }
        if ((tid & 31) == 0) { s_v[tid >> 5] = bv; s_i[tid >> 5] = bi; }
        __syncthreads();
        if (lt == 0) {
            const int base = g * 4;
            float fv = s_v[base]; int fi = s_i[base];
            #pragma unroll
            for (int wv = 1; wv < 4; wv++) {
                float v2 = s_v[base + wv]; int i2 = s_i[base + wv];
                if (v2 > fv || (v2 == fv && i2 < fi)) { fv = v2; fi = i2; }
            }
            top_idx[g][r] = fi;
        }
        __syncthreads();
    }

    // Full-spectrum ranks {0, 2} from half-spectrum top-3 with pair multiplicity:
    // DC (0) and Nyquist (1250) appear once; other bins twice (k, 2500-k).
    const int h0 = top_idx[g][0], h1 = top_idx[g][1], h2 = top_idx[g][2];
    const bool h0_pair = (h0 != 0 && h0 != 1250);
    const bool h1_pair = (h1 != 0 && h1 != 1250);
    const int ka = h0;
    const int kb = (h0_pair || h1_pair) ? h1 : h2;

    if (lt < PATCHES) {
        const float wgt = 12.0f * wscal[0];  // N * weights
        const int start = lt * 50;
        int cnt = 0;
        if (ka != 0) {
            int p = L / ka;
            int fm = ((start + p - 1) / p) * p;
            cnt += (fm < start + 50);
        }
        if (kb != 0) {
            int p = L / kb;
            int fm = ((start + p - 1) / p) * p;
            cnt += (fm < start + 50);
        }
        out[(b0 + g) * PATCHES + lt] = wgt * (float)cnt;
    }
}

extern "C" void kernel_launch(void* const* d_in, const int* in_sizes, int n_in,
                              void* d_out, int out_size) {
    const float* x = (const float*)d_in[0];
    const float* w = (const float*)d_in[1];
    int xs = in_sizes[0];
    if (n_in >= 2 && in_sizes[0] < in_sizes[1]) {  // order-robust: scalar vs big tensor
        x = (const float*)d_in[1];
        w = (const float*)d_in[0];
        xs = in_sizes[1];
    }
    const int B = xs / (12 * L);   // 1024
    TimeSeriesWeighting_kernel<<<B / 2, THREADS>>>(x, w, (float*)d_out);
}

// round 15
// speedup vs baseline: 1.1552x; 1.0172x over previous
#include <cuda_runtime.h>

#define THREADS 256
#define L 2500
#define HALF 1251          // bins 0..1250
#define PATCHES 50
#define TWN 500            // master twiddle table: W_2500^j, j=0..499
#define GROUP 64           // threads per batch in the search phase

#define CR1 ( 0.30901699437494742f)
#define CR2 (-0.80901699437494742f)
#define SI1 ( 0.95105651629515357f)
#define SI2 ( 0.58778525229247314f)

__device__ __forceinline__ float2 cmul(float2 a, float2 b) {
    return make_float2(a.x * b.x - a.y * b.y, a.x * b.y + a.y * b.x);
}

// DFT-5 core (pre-twiddle outputs) on one complex value set.
__device__ __forceinline__ void dft5(float2 a0, float2 a1, float2 a2, float2 a3, float2 a4,
                                     float2& c0, float2& c1, float2& c2, float2& c3, float2& c4) {
    float2 t1 = make_float2(a1.x + a4.x, a1.y + a4.y);
    float2 t2 = make_float2(a2.x + a3.x, a2.y + a3.y);
    float2 t3 = make_float2(a1.x - a4.x, a1.y - a4.y);
    float2 t4 = make_float2(a2.x - a3.x, a2.y - a3.y);
    c0 = make_float2(a0.x + t1.x + t2.x, a0.y + t1.y + t2.y);
    float2 m1 = make_float2(a0.x + CR1 * t1.x + CR2 * t2.x, a0.y + CR1 * t1.y + CR2 * t2.y);
    float2 m2 = make_float2(a0.x + CR2 * t1.x + CR1 * t2.x, a0.y + CR2 * t1.y + CR1 * t2.y);
    float2 s1 = make_float2(SI1 * t3.x + SI2 * t4.x, SI1 * t3.y + SI2 * t4.y);
    float2 s2 = make_float2(SI2 * t3.x - SI1 * t4.x, SI2 * t3.y - SI1 * t4.y);
    c1 = make_float2(m1.x + s1.y, m1.y - s1.x);
    c4 = make_float2(m1.x - s1.y, m1.y + s1.x);
    c2 = make_float2(m2.x + s2.y, m2.y - s2.x);
    c3 = make_float2(m2.x - s2.y, m2.y + s2.x);
}

// Dual radix-5 butterfly on interleaved float4 (two packed FFTs), shared twiddles.
__device__ __forceinline__ void bf5x2(float4 A0, float4 A1, float4 A2, float4 A3, float4 A4,
                                      float2 w1, float4* __restrict__ Y, int ob, int SS) {
    float2 p0, p1, p2, p3, p4, q0, q1, q2, q3, q4;
    dft5(make_float2(A0.x, A0.y), make_float2(A1.x, A1.y), make_float2(A2.x, A2.y),
         make_float2(A3.x, A3.y), make_float2(A4.x, A4.y), p0, p1, p2, p3, p4);
    dft5(make_float2(A0.z, A0.w), make_float2(A1.z, A1.w), make_float2(A2.z, A2.w),
         make_float2(A3.z, A3.w), make_float2(A4.z, A4.w), q0, q1, q2, q3, q4);
    float2 w2 = cmul(w1, w1);
    float2 w3 = cmul(w2, w1);
    float2 w4 = cmul(w2, w2);
    Y[ob] = make_float4(p0.x, p0.y, q0.x, q0.y);
    float2 r, s;
    r = cmul(p1, w1); s = cmul(q1, w1); Y[ob + SS]     = make_float4(r.x, r.y, s.x, s.y);
    r = cmul(p2, w2); s = cmul(q2, w2); Y[ob + 2 * SS] = make_float4(r.x, r.y, s.x, s.y);
    r = cmul(p3, w3); s = cmul(q3, w3); Y[ob + 3 * SS] = make_float4(r.x, r.y, s.x, s.y);
    r = cmul(p4, w4); s = cmul(q4, w4); Y[ob + 4 * SS] = make_float4(r.x, r.y, s.x, s.y);
}

// Stockham DIF radix-5 stage on the dual-FFT float4 buffers. WORK = 500 each.
template <int NN, int SS>
__device__ __forceinline__ void stage5x2(const float4* __restrict__ X, float4* __restrict__ Y,
                                         const float2* __restrict__ tw, int tid) {
    constexpr int M = NN / 5;
    constexpr int STRIDE = 2500 / NN;
    for (int w = tid; w < M * SS; w += THREADS) {
        const int q = w % SS;
        const int p = w / SS;
        bf5x2(X[q + SS * p], X[q + SS * (p + M)], X[q + SS * (p + 2 * M)],
              X[q + SS * (p + 3 * M)], X[q + SS * (p + 4 * M)],
              tw[p * STRIDE], Y, q + SS * 5 * p, SS);
    }
}

// Dual final radix-4 DIF butterfly (twiddle-free).
__device__ __forceinline__ void r4x2(const float4* __restrict__ A, int q,
                                     float4& z0, float4& z1, float4& z2, float4& z3) {
    float4 a0 = A[q], a1 = A[q + 625], a2 = A[q + 1250], a3 = A[q + 1875];
    float4 e0 = make_float4(a0.x + a2.x, a0.y + a2.y, a0.z + a2.z, a0.w + a2.w);
    float4 e1 = make_float4(a0.x - a2.x, a0.y - a2.y, a0.z - a2.z, a0.w - a2.w);
    float4 o0 = make_float4(a1.x + a3.x, a1.y + a3.y, a1.z + a3.z, a1.w + a3.w);
    float4 o1 = make_float4(a1.x - a3.x, a1.y - a3.y, a1.z - a3.z, a1.w - a3.w);
    z0 = make_float4(e0.x + o0.x, e0.y + o0.y, e0.z + o0.z, e0.w + o0.w);   // Z[q]
    z1 = make_float4(e1.x + o1.y, e1.y - o1.x, e1.z + o1.w, e1.w - o1.z);   // Z[q+625]
    z2 = make_float4(e0.x - o0.x, e0.y - o0.y, e0.z - o0.z, e0.w - o0.w);   // Z[q+1250]
    z3 = make_float4(e1.x - o1.y, e1.y + o1.x, e1.z - o1.w, e1.w + o1.z);   // Z[q+1875]
}

__global__ __launch_bounds__(THREADS)
void TimeSeriesWeighting_kernel(const float* __restrict__ x,
                                const float* __restrict__ wscal,
                                float* __restrict__ out) {
    extern __shared__ float4 smem4[];
    float4* bA = smem4;            // 2500 float4 (dual FFT, interleaved)
    float4* bB = smem4 + 2500;     // 2500 float4
    float2* tw = reinterpret_cast<float2*>(smem4 + 5000);   // 500 float2
    __shared__ float s_v[THREADS / 32];
    __shared__ int   s_i[THREADS / 32];
    __shared__ int   top_idx[4][3];

    const int tid = threadIdx.x;
    const long long b0 = 4LL * blockIdx.x;
    const float* xa = x + b0 * 30000;
    const float* xb = xa + 30000;
    const float* xc = xa + 60000;
    const float* xd = xa + 90000;

    // Fused load + stage 1 (NN=2500, SS=1): gmem loads issue at cycle 0;
    // stage-1 twiddle computed inline (MUFU). z1 = xa + i*xb, z2 = xc + i*xd.
    for (int p = tid; p < 500; p += THREADS) {
        float4 A0 = make_float4(xa[p],        xb[p],        xc[p],        xd[p]);
        float4 A1 = make_float4(xa[p +  500], xb[p +  500], xc[p +  500], xd[p +  500]);
        float4 A2 = make_float4(xa[p + 1000], xb[p + 1000], xc[p + 1000], xd[p + 1000]);
        float4 A3 = make_float4(xa[p + 1500], xb[p + 1500], xc[p + 1500], xd[p + 1500]);
        float4 A4 = make_float4(xa[p + 2000], xb[p + 2000], xc[p + 2000], xd[p + 2000]);
        float sn, cs;
        __sincosf(-6.283185307179586f * (float)p * (1.0f / 2500.0f), &sn, &cs);
        bf5x2(A0, A1, A2, A3, A4, make_float2(cs, sn), bB, 5 * p, 1);
    }
    // Master twiddle table fill overlaps the stage-1 gmem latency tail.
    for (int j = tid; j < TWN; j += THREADS) {
        float sn, cs;
        __sincosf(-6.283185307179586f * (float)j * (1.0f / 2500.0f), &sn, &cs);
        tw[j] = make_float2(cs, sn);
    }
    __syncthreads();

    // Remaining Stockham stages (natural-order autosort)
    stage5x2<500, 5>(bB, bA, tw, tid);   __syncthreads();
    stage5x2<100, 25>(bA, bB, tw, tid);  __syncthreads();
    stage5x2<20, 125>(bB, bA, tw, tid);  __syncthreads();

    // Fused final radix-4 + conjugate-split + power for all 4 batches.
    // Butterflies q and 625-q jointly produce the 4 conjugate pairs covering
    // half-bins {q, 625-q, 625+q, 1250-q} (verified R10-R14).
    float* pwbase = reinterpret_cast<float*>(bB);   // 10000 floats available
    float* pa1 = pwbase;           // batch a
    float* pb1 = pwbase + 1280;    // batch b
    float* pa2 = pwbase + 2560;    // batch c
    float* pb2 = pwbase + 3840;    // batch d

    #define PAIRPOW2(zk, zm, kk) do {                                         \
        float sx = (zk).x + (zm).x, sy = (zk).y - (zm).y;                     \
        float dx = (zk).x - (zm).x, dy = (zk).y + (zm).y;                     \
        pa1[(kk)] = sx * sx + sy * sy;                                        \
        pb1[(kk)] = dx * dx + dy * dy;                                        \
        float sz = (zk).z + (zm).z, sw = (zk).w - (zm).w;                     \
        float dz = (zk).z - (zm).z, dw = (zk).w + (zm).w;                     \
        pa2[(kk)] = sz * sz + sw * sw;                                        \
        pb2[(kk)] = dz * dz + dw * dw;                                        \
    } while (0)

    for (int w = tid; w < 313; w += THREADS) {
        if (w == 0) {
            // self-paired butterfly 0: bins 0, 625 (pairs with 1875), 1250
            float4 z0, z1, z2, z3;
            r4x2(bA, 0, z0, z1, z2, z3);
            PAIRPOW2(z0, z0, 0);
            PAIRPOW2(z1, z3, 625);
            PAIRPOW2(z2, z2, 1250);
        } else {
            const int q = w;              // 1..312
            float4 q0, q1, q2, q3, p0, p1v, p2, p3;
            r4x2(bA, q, q0, q1, q2, q3);
            r4x2(bA, 625 - q, p0, p1v, p2, p3);
            PAIRPOW2(q0, p3, q);           // Z[q]      & Z[2500-q]
            PAIRPOW2(p0, q3, 625 - q);     // Z[625-q]  & Z[1875+q]
            PAIRPOW2(q1, p2, 625 + q);     // Z[625+q]  & Z[1875-q]
            PAIRPOW2(p1v, q2, 1250 - q);   // Z[1250-q] & Z[1250+q]
        }
    }
    #undef PAIRPOW2
    __syncthreads();

    // Top-3 half-spectrum bins per batch; 4 groups of 64 threads, one per batch.
    // 3 exclusion passes (proven fastest search scheme).
    const int g = tid >> 6;           // 0..3 -> batches a,b,c,d
    const int lt = tid & 63;
    const float* pw = pwbase + g * 1280;
    for (int r = 0; r < 3; r++) {
        const int e0 = (r > 0) ? top_idx[g][0] : -1;
        const int e1 = (r > 1) ? top_idx[g][1] : -1;
        float bv = -1.0f;
        int bi = 0x7fffffff;
        for (int k = lt; k < HALF; k += GROUP) {
            if (k == e0 || k == e1) continue;
            float v = pw[k];
            if (v > bv || (v == bv && k < bi)) { bv = v; bi = k; }
        }
        #pragma unroll
        for (int off = 16; off > 0; off >>= 1) {
            float ov = __shfl_down_sync(0xffffffffu, bv, off);
            int   oi = __shfl_down_sync(0xffffffffu, bi, off);
            if (ov > bv || (ov == bv && oi < bi)) { bv = ov; bi = oi; }
        }
        if ((tid & 31) == 0) { s_v[tid >> 5] = bv; s_i[tid >> 5] = bi; }
        __syncthreads();
        if (lt == 0) {
            const int base = g * 2;       // group g owns warps 2g, 2g+1
            float fv = s_v[base]; int fi = s_i[base];
            float v2 = s_v[base + 1]; int i2 = s_i[base + 1];
            if (v2 > fv || (v2 == fv && i2 < fi)) { fv = v2; fi = i2; }
            top_idx[g][r] = fi;
        }
        __syncthreads();
    }

    // Full-spectrum ranks {0, 2} from half-spectrum top-3 with pair multiplicity:
    // DC (0) and Nyquist (1250) appear once; other bins twice (k, 2500-k).
    const int h0 = top_idx[g][0], h1 = top_idx[g][1], h2 = top_idx[g][2];
    const bool h0_pair = (h0 != 0 && h0 != 1250);
    const bool h1_pair = (h1 != 0 && h1 != 1250);
    const int ka = h0;
    const int kb = (h0_pair || h1_pair) ? h1 : h2;

    if (lt < PATCHES) {
        const float wgt = 12.0f * wscal[0];  // N * weights
        const int start = lt * 50;
        int cnt = 0;
        if (ka != 0) {
            int p = L / ka;
            int fm = ((start + p - 1) / p) * p;
            cnt += (fm < start + 50);
        }
        if (kb != 0) {
            int p = L / kb;
            int fm = ((start + p - 1) / p) * p;
            cnt += (fm < start + 50);
        }
        out[(b0 + g) * PATCHES + lt] = wgt * (float)cnt;
    }
}

extern "C" void kernel_launch(void* const* d_in, const int* in_sizes, int n_in,
                              void* d_out, int out_size) {
    const float* x = (const float*)d_in[0];
    const float* w = (const float*)d_in[1];
    int xs = in_sizes[0];
    if (n_in >= 2 && in_sizes[0] < in_sizes[1]) {  // order-robust: scalar vs big tensor
        x = (const float*)d_in[1];
        w = (const float*)d_in[0];
        xs = in_sizes[1];
    }
    const int B = xs / (12 * L);   // 1024
    const int smem_bytes = 5000 * (int)sizeof(float4) + TWN * (int)sizeof(float2);  // 84000
    cudaFuncSetAttribute(TimeSeriesWeighting_kernel,
                         cudaFuncAttributeMaxDynamicSharedMemorySize, smem_bytes);
    TimeSeriesWeighting_kernel<<<B / 4, THREADS, smem_bytes>>>(x, w, (float*)d_out);
}